// round 2
// baseline (speedup 1.0000x reference)
#include <cuda_runtime.h>
#include <math.h>

#define BB 16
#define TT_SEQ 4096
#define DD 512
#define SUBD 256
#define KK 1024
#define NROW (BB * TT_SEQ)          // 65536
#define NTOT (BB * DD * TT_SEQ)     // 33554432

#define T_TILE 64
#define K_TILE 128
#define THREADS 256
#define NBLOCKS ((NROW) / T_TILE)   // 1024

// dynamic smem layout (floats):
// sX: 256*64 | sE: 256*128 | sH: 128 | sXn: 64 | sBV: 1024 | sBI: 1024 | sIdx: 64 | sP: 256
#define SMEM_FLOATS (SUBD*T_TILE + SUBD*K_TILE + K_TILE + T_TILE + T_TILE*16 + T_TILE*16 + T_TILE + 4*T_TILE)
#define SMEM_BYTES (SMEM_FLOATS * 4)

__device__ float  g_eT[2][SUBD * KK];   // transposed codebooks: [d][k]
__device__ float  g_h[2][KK];           // ||e_k||^2
__device__ int    g_cnt[2][KK];
__device__ double g_loss;

// ---------------------------------------------------------------- helpers

__device__ __forceinline__ unsigned long long dup2(float v) {
    unsigned long long r;
    unsigned u = __float_as_uint(v);
    asm("mov.b64 %0, {%1, %1};" : "=l"(r) : "r"(u));
    return r;
}

#define FFMA2(acc, a, b) \
    asm("fma.rn.f32x2 %0, %1, %2, %0;" : "+l"(acc) : "l"(a), "l"(b))

// ---------------------------------------------------------------- init

__global__ void init_k() {
    int i = blockIdx.x * blockDim.x + threadIdx.x;
    if (i < 2 * KK) ((int*)g_cnt)[i] = 0;
    if (i == 0) g_loss = 0.0;
}

// ---------------------------------------------------------------- transpose emb -> g_eT [d][k]

__global__ void transpose_k(const float* __restrict__ e1, const float* __restrict__ e2) {
    __shared__ float tile[32][33];
    int c = blockIdx.z;
    const float* src = c ? e2 : e1;
    int row0 = blockIdx.y * 32;   // k
    int col0 = blockIdx.x * 32;   // d
    int tx = threadIdx.x, ty = threadIdx.y;    // 32 x 8
    #pragma unroll
    for (int j = 0; j < 32; j += 8)
        tile[ty + j][tx] = src[(size_t)(row0 + ty + j) * SUBD + col0 + tx];
    __syncthreads();
    #pragma unroll
    for (int j = 0; j < 32; j += 8)
        g_eT[c][(size_t)(col0 + ty + j) * KK + row0 + tx] = tile[tx][ty + j];
}

// ---------------------------------------------------------------- codeword norms

__global__ void norm_k(const float* __restrict__ e1, const float* __restrict__ e2) {
    int warp = threadIdx.x >> 5, lane = threadIdx.x & 31;
    int c = blockIdx.x >> 7;
    int row = ((blockIdx.x & 127) << 3) + warp;
    const float* src = c ? e2 : e1;
    const float4* r = (const float4*)(src + (size_t)row * SUBD);
    float4 a = r[lane], b = r[lane + 32];
    float s = a.x*a.x + a.y*a.y + a.z*a.z + a.w*a.w
            + b.x*b.x + b.y*b.y + b.z*b.z + b.w*b.w;
    #pragma unroll
    for (int o = 16; o; o >>= 1) s += __shfl_down_sync(0xffffffffu, s, o);
    if (lane == 0) g_h[c][row] = s;
}

// ---------------------------------------------------------------- main VQ kernel

__global__ void __launch_bounds__(THREADS, 1) vq_main(
    const float* __restrict__ x, const float* __restrict__ emb1,
    const float* __restrict__ emb2, float* __restrict__ out)
{
    extern __shared__ float sm[];
    float* sX   = sm;                           // [256][64]  x tile, d-major, t contiguous
    float* sE   = sX + SUBD * T_TILE;           // [256][128] codebook tile, d-major, k contiguous
    float* sH   = sE + SUBD * K_TILE;           // [128]
    float* sXn  = sH + K_TILE;                  // [64] row norms
    float* sBV  = sXn + T_TILE;                 // [64][16]
    int*   sBI  = (int*)(sBV + T_TILE * 16);    // [64][16]
    int*   sIdx = sBI + T_TILE * 16;            // [64]
    float* sP   = (float*)(sIdx + T_TILE);      // [4][64] partial norms
    __shared__ float warp_l[8];

    int tid = threadIdx.x;
    int tg = tid >> 4;        // 0..15 -> t group (4 t's)
    int kg = tid & 15;        // 0..15 -> k group (8 k's)
    int blk = blockIdx.x;
    int b = blk >> 6;
    int t0 = (blk & 63) * T_TILE;

    float loss_acc = 0.f;

    for (int phase = 0; phase < 2; ++phase) {
        const float* xg   = x + ((size_t)b * DD + phase * SUBD) * TT_SEQ + t0;
        const float* eT   = g_eT[phase];
        const float* hh   = g_h[phase];
        const float* embp = phase ? emb2 : emb1;

        // ---- load x tile (coalesced, conflict-free) ----
        for (int i = tid; i < SUBD * 16; i += THREADS) {
            int d = i >> 4, seg = i & 15;
            *(float4*)&sX[d * T_TILE + seg * 4] =
                *(const float4*)&xg[(size_t)d * TT_SEQ + seg * 4];
        }
        __syncthreads();

        // ---- row norms X[t] = sum_d x^2 (deterministic 4-chunk order) ----
        {
            int t = tid & 63, c = tid >> 6;
            float s = 0.f;
            #pragma unroll 8
            for (int d = c * 64; d < c * 64 + 64; ++d) {
                float v = sX[d * T_TILE + t];
                s = fmaf(v, v, s);
            }
            sP[c * T_TILE + t] = s;
        }
        __syncthreads();
        if (tid < T_TILE)
            sXn[tid] = ((sP[tid] + sP[T_TILE + tid]) + sP[2 * T_TILE + tid]) + sP[3 * T_TILE + tid];
        __syncthreads();

        float Xn[4];
        #pragma unroll
        for (int i = 0; i < 4; i++) Xn[i] = sXn[tg * 4 + i];

        float bestv[4]; int besti[4];
        #pragma unroll
        for (int i = 0; i < 4; i++) { bestv[i] = 3.4e38f; besti[i] = 0; }

        // ---- K tiles ----
        for (int kt = 0; kt < KK / K_TILE; ++kt) {
            int kbase = kt * K_TILE;
            __syncthreads();   // previous tile fully consumed
            for (int i = tid; i < SUBD * 32; i += THREADS) {
                int d = i >> 5, c = i & 31;
                *(float4*)&sE[d * K_TILE + c * 4] =
                    *(const float4*)&eT[(size_t)d * KK + kbase + c * 4];
            }
            if (tid < K_TILE) sH[tid] = hh[kbase + tid];
            __syncthreads();

            unsigned long long acc[4][4];
            #pragma unroll
            for (int i = 0; i < 4; i++)
                #pragma unroll
                for (int j = 0; j < 4; j++) acc[i][j] = 0ULL;

            const float* xp = &sX[tg * 4];
            const float* ep = &sE[kg * 8];
            #pragma unroll 4
            for (int d = 0; d < SUBD; ++d) {
                float4 xf = *(const float4*)(xp + d * T_TILE);
                ulonglong2 eA = *(const ulonglong2*)(ep + d * K_TILE);      // k+0..3 packed
                ulonglong2 eB = *(const ulonglong2*)(ep + d * K_TILE + 4);  // k+4..7 packed
                unsigned long long x0 = dup2(xf.x), x1 = dup2(xf.y);
                unsigned long long x2 = dup2(xf.z), x3 = dup2(xf.w);
                FFMA2(acc[0][0], x0, eA.x); FFMA2(acc[0][1], x0, eA.y);
                FFMA2(acc[0][2], x0, eB.x); FFMA2(acc[0][3], x0, eB.y);
                FFMA2(acc[1][0], x1, eA.x); FFMA2(acc[1][1], x1, eA.y);
                FFMA2(acc[1][2], x1, eB.x); FFMA2(acc[1][3], x1, eB.y);
                FFMA2(acc[2][0], x2, eA.x); FFMA2(acc[2][1], x2, eA.y);
                FFMA2(acc[2][2], x2, eB.x); FFMA2(acc[2][3], x2, eB.y);
                FFMA2(acc[3][0], x3, eA.x); FFMA2(acc[3][1], x3, eA.y);
                FFMA2(acc[3][2], x3, eB.x); FFMA2(acc[3][3], x3, eB.y);
            }

            // distances exactly in reference form: fl(fl(X - 2s) + h); ascending-k, strict <
            #pragma unroll
            for (int i = 0; i < 4; i++) {
                #pragma unroll
                for (int j = 0; j < 4; j++) {
                    float s0 = __uint_as_float((unsigned)(acc[i][j]));
                    float s1 = __uint_as_float((unsigned)(acc[i][j] >> 32));
                    int k0 = kbase + kg * 8 + j * 2;
                    float h0 = sH[kg * 8 + j * 2];
                    float h1 = sH[kg * 8 + j * 2 + 1];
                    float d0 = __fmaf_rn(-2.f, s0, Xn[i]) + h0;
                    float d1 = __fmaf_rn(-2.f, s1, Xn[i]) + h1;
                    if (d0 < bestv[i]) { bestv[i] = d0; besti[i] = k0; }
                    if (d1 < bestv[i]) { bestv[i] = d1; besti[i] = k0 + 1; }
                }
            }
        }

        // ---- argmin reduction across kg threads (lowest index wins ties) ----
        #pragma unroll
        for (int i = 0; i < 4; i++) {
            sBV[(tg * 4 + i) * 16 + kg] = bestv[i];
            sBI[(tg * 4 + i) * 16 + kg] = besti[i];
        }
        __syncthreads();
        if (tid < T_TILE) {
            float bv = sBV[tid * 16]; int bi = sBI[tid * 16];
            #pragma unroll
            for (int j = 1; j < 16; j++) {
                float v = sBV[tid * 16 + j]; int ii = sBI[tid * 16 + j];
                if (v < bv || (v == bv && ii < bi)) { bv = v; bi = ii; }
            }
            sIdx[tid] = bi;
            atomicAdd(&g_cnt[phase][bi], 1);
        }
        __syncthreads();

        // ---- stage quant rows into smem (reuse sE), layout [d][t] like sX ----
        float* sQ = sE;
        for (int i = tid; i < T_TILE * 64; i += THREADS) {
            int t = i & 63, ds = i >> 6;
            float4 q = *(const float4*)&embp[(size_t)sIdx[t] * SUBD + ds * 4];
            sQ[(ds * 4 + 0) * T_TILE + t] = q.x;
            sQ[(ds * 4 + 1) * T_TILE + t] = q.y;
            sQ[(ds * 4 + 2) * T_TILE + t] = q.z;
            sQ[(ds * 4 + 3) * T_TILE + t] = q.w;
        }
        __syncthreads();

        // ---- write output (straight-through form x + (q - x)) + loss ----
        float* og = out + ((size_t)b * DD + phase * SUBD) * TT_SEQ + t0;
        for (int i = tid; i < SUBD * 16; i += THREADS) {
            int d = i >> 4, seg = i & 15;
            float4 q  = *(const float4*)&sQ[d * T_TILE + seg * 4];
            float4 xv = *(const float4*)&sX[d * T_TILE + seg * 4];
            float d0 = q.x - xv.x, d1 = q.y - xv.y, d2 = q.z - xv.z, d3 = q.w - xv.w;
            loss_acc += d0 * d0 + d1 * d1 + d2 * d2 + d3 * d3;
            float4 o;
            o.x = xv.x + d0; o.y = xv.y + d1; o.z = xv.z + d2; o.w = xv.w + d3;
            *(float4*)&og[(size_t)d * TT_SEQ + seg * 4] = o;
        }
        __syncthreads();   // before next phase reuses sX / sE
    }

    // ---- block loss reduction -> double atomic ----
    #pragma unroll
    for (int o = 16; o; o >>= 1) loss_acc += __shfl_down_sync(0xffffffffu, loss_acc, o);
    if ((tid & 31) == 0) warp_l[tid >> 5] = loss_acc;
    __syncthreads();
    if (tid == 0) {
        float s = 0.f;
        #pragma unroll
        for (int w = 0; w < 8; w++) s += warp_l[w];
        atomicAdd(&g_loss, (double)s);
    }
}

// ---------------------------------------------------------------- scalars

__global__ void finalize_k(float* __restrict__ out) {
    __shared__ double red0[8], red1[8];
    int tid = threadIdx.x;
    double s0 = 0.0, s1 = 0.0;
    for (int k = tid; k < KK; k += 256) {
        double p0 = (double)g_cnt[0][k] / (double)NROW;
        double p1 = (double)g_cnt[1][k] / (double)NROW;
        s0 += p0 * log(p0 + 1e-10);
        s1 += p1 * log(p1 + 1e-10);
    }
    #pragma unroll
    for (int o = 16; o; o >>= 1) {
        s0 += __shfl_down_sync(0xffffffffu, s0, o);
        s1 += __shfl_down_sync(0xffffffffu, s1, o);
    }
    if ((tid & 31) == 0) { red0[tid >> 5] = s0; red1[tid >> 5] = s1; }
    __syncthreads();
    if (tid == 0) {
        double e0 = 0.0, e1 = 0.0;
        #pragma unroll
        for (int w = 0; w < 8; w++) { e0 += red0[w]; e1 += red1[w]; }
        double perp = exp(-e0) + exp(-e1);
        double vq = 1.25 * g_loss / (double)NTOT;
        out[NTOT]     = (float)vq;
        out[NTOT + 1] = (float)perp;
    }
}

// ---------------------------------------------------------------- launch

extern "C" void kernel_launch(void* const* d_in, const int* in_sizes, int n_in,
                              void* d_out, int out_size) {
    const float* x  = (const float*)d_in[0];
    const float* e1 = (const float*)d_in[1];
    const float* e2 = (const float*)d_in[2];
    float* out = (float*)d_out;

    cudaFuncSetAttribute(vq_main, cudaFuncAttributeMaxDynamicSharedMemorySize, SMEM_BYTES);

    init_k<<<8, 256>>>();
    transpose_k<<<dim3(SUBD / 32, KK / 32, 2), dim3(32, 8)>>>(e1, e2);
    norm_k<<<256, 256>>>(e1, e2);
    vq_main<<<NBLOCKS, THREADS, SMEM_BYTES>>>(x, e1, e2, out);
    if (out_size >= NTOT + 2)
        finalize_k<<<1, 256>>>(out);
}

// round 4
// speedup vs baseline: 1.2174x; 1.2174x over previous
#include <cuda_runtime.h>
#include <math.h>

#define BB 16
#define TT_SEQ 4096
#define DD 512
#define SUBD 256
#define KK 1024
#define NROW (BB * TT_SEQ)          // 65536
#define NTOT (BB * DD * TT_SEQ)     // 33554432

#define T_TILE 64
#define K_TILE 128
#define THREADS 128
#define NBLOCKS ((NROW) / T_TILE)   // 1024

// dynamic smem layout (floats):
// sX: 256*64 | sE: 256*128 | sH: 128 | sXn: 64 | sBV: 1024 | sBI: 1024 | sIdx: 64 | sP: 256
#define SMEM_FLOATS (SUBD*T_TILE + SUBD*K_TILE + K_TILE + T_TILE + T_TILE*16 + T_TILE*16 + T_TILE + 4*T_TILE)
#define SMEM_BYTES (SMEM_FLOATS * 4)

__device__ float  g_eT[2][SUBD * KK];   // transposed codebooks: [d][k]
__device__ float  g_h[2][KK];           // ||e_k||^2
__device__ int    g_cnt[2][KK];
__device__ double g_loss;

// ---------------------------------------------------------------- helpers

__device__ __forceinline__ unsigned long long dup2(float v) {
    unsigned long long r;
    unsigned u = __float_as_uint(v);
    asm("mov.b64 %0, {%1, %1};" : "=l"(r) : "r"(u));
    return r;
}

#define FFMA2(acc, a, b) \
    asm("fma.rn.f32x2 %0, %1, %2, %0;" : "+l"(acc) : "l"(a), "l"(b))

// ---------------------------------------------------------------- init

__global__ void init_k() {
    int i = blockIdx.x * blockDim.x + threadIdx.x;
    if (i < 2 * KK) ((int*)g_cnt)[i] = 0;
    if (i == 0) g_loss = 0.0;
}

// ---------------------------------------------------------------- transpose emb -> g_eT [d][k]

__global__ void transpose_k(const float* __restrict__ e1, const float* __restrict__ e2) {
    __shared__ float tile[32][33];
    int c = blockIdx.z;
    const float* src = c ? e2 : e1;
    int row0 = blockIdx.y * 32;   // k
    int col0 = blockIdx.x * 32;   // d
    int tx = threadIdx.x, ty = threadIdx.y;    // 32 x 8
    #pragma unroll
    for (int j = 0; j < 32; j += 8)
        tile[ty + j][tx] = src[(size_t)(row0 + ty + j) * SUBD + col0 + tx];
    __syncthreads();
    #pragma unroll
    for (int j = 0; j < 32; j += 8)
        g_eT[c][(size_t)(col0 + ty + j) * KK + row0 + tx] = tile[tx][ty + j];
}

// ---------------------------------------------------------------- codeword norms

__global__ void norm_k(const float* __restrict__ e1, const float* __restrict__ e2) {
    int warp = threadIdx.x >> 5, lane = threadIdx.x & 31;
    int c = blockIdx.x >> 7;
    int row = ((blockIdx.x & 127) << 3) + warp;
    const float* src = c ? e2 : e1;
    const float4* r = (const float4*)(src + (size_t)row * SUBD);
    float4 a = r[lane], b = r[lane + 32];
    float s = a.x*a.x + a.y*a.y + a.z*a.z + a.w*a.w
            + b.x*b.x + b.y*b.y + b.z*b.z + b.w*b.w;
    #pragma unroll
    for (int o = 16; o; o >>= 1) s += __shfl_down_sync(0xffffffffu, s, o);
    if (lane == 0) g_h[c][row] = s;
}

// ---------------------------------------------------------------- main VQ kernel
// 128 threads: tg = tid>>4 (8 groups of 8 t), kg = tid&15 (16 groups of 8 k).
// Thread kg owns k in {4kg..4kg+3} and {64+4kg..64+4kg+3} within each K tile
// (contiguous 16B per LDS lane -> conflict-free crossbar rows).
// Accumulators pack two adjacent t per f32x2 register: 4 t-pairs x 8 k = 32 FFMA2/d.

__global__ void __launch_bounds__(THREADS, 1) vq_main(
    const float* __restrict__ x, const float* __restrict__ emb1,
    const float* __restrict__ emb2, float* __restrict__ out)
{
    extern __shared__ float sm[];
    float* sX   = sm;                           // [256][64]  x tile, d-major, t contiguous
    float* sE   = sX + SUBD * T_TILE;           // [256][128] codebook tile, d-major, k contiguous
    float* sH   = sE + SUBD * K_TILE;           // [128]
    float* sXn  = sH + K_TILE;                  // [64] row norms
    float* sBV  = sXn + T_TILE;                 // [64][16]
    int*   sBI  = (int*)(sBV + T_TILE * 16);    // [64][16]
    int*   sIdx = sBI + T_TILE * 16;            // [64]
    float* sP   = (float*)(sIdx + T_TILE);      // [4][64] partial norms
    __shared__ float warp_l[4];

    int tid = threadIdx.x;
    int tg = tid >> 4;        // 0..7  -> t group (8 t's)
    int kg = tid & 15;        // 0..15 -> k group (8 k's, split 4+4)
    int blk = blockIdx.x;
    int b = blk >> 6;
    int t0 = (blk & 63) * T_TILE;

    float loss_acc = 0.f;

    for (int phase = 0; phase < 2; ++phase) {
        const float* xg   = x + ((size_t)b * DD + phase * SUBD) * TT_SEQ + t0;
        const float* eT   = g_eT[phase];
        const float* hh   = g_h[phase];
        const float* embp = phase ? emb2 : emb1;

        // ---- load x tile (coalesced, conflict-free) ----
        for (int i = tid; i < SUBD * 16; i += THREADS) {
            int d = i >> 4, seg = i & 15;
            *(float4*)&sX[d * T_TILE + seg * 4] =
                *(const float4*)&xg[(size_t)d * TT_SEQ + seg * 4];
        }
        __syncthreads();

        // ---- row norms X[t]: EXACT same 4x64-chunk grouping as the passing version ----
        for (int job = tid; job < 4 * T_TILE; job += THREADS) {
            int t = job & 63, c = job >> 6;
            float s = 0.f;
            #pragma unroll 8
            for (int d = c * 64; d < c * 64 + 64; ++d) {
                float v = sX[d * T_TILE + t];
                s = fmaf(v, v, s);
            }
            sP[c * T_TILE + t] = s;
        }
        __syncthreads();
        if (tid < T_TILE)
            sXn[tid] = ((sP[tid] + sP[T_TILE + tid]) + sP[2 * T_TILE + tid]) + sP[3 * T_TILE + tid];
        __syncthreads();

        float Xn[8];
        #pragma unroll
        for (int i = 0; i < 8; i++) Xn[i] = sXn[tg * 8 + i];

        float bestv[8]; int besti[8];
        #pragma unroll
        for (int i = 0; i < 8; i++) { bestv[i] = 3.4e38f; besti[i] = 0; }

        // ---- K tiles ----
        for (int kt = 0; kt < KK / K_TILE; ++kt) {
            int kbase = kt * K_TILE;
            __syncthreads();   // previous tile fully consumed
            for (int i = tid; i < SUBD * 32; i += THREADS) {
                int d = i >> 5, c = i & 31;
                *(float4*)&sE[d * K_TILE + c * 4] =
                    *(const float4*)&eT[(size_t)d * KK + kbase + c * 4];
            }
            sH[tid] = hh[kbase + tid];
            __syncthreads();

            // acc[tp][j]: tp = t-pair (t = tg*8 + 2tp {+1}), j = k slot
            unsigned long long acc[4][8];
            #pragma unroll
            for (int i = 0; i < 4; i++)
                #pragma unroll
                for (int j = 0; j < 8; j++) acc[i][j] = 0ULL;

            const float* xp  = &sX[tg * 8];
            const float* epA = &sE[kg * 4];
            const float* epB = &sE[64 + kg * 4];
            #pragma unroll 4
            for (int d = 0; d < SUBD; ++d) {
                ulonglong2 xa = *(const ulonglong2*)(xp + d * T_TILE);      // t-pairs 0,1
                ulonglong2 xb = *(const ulonglong2*)(xp + d * T_TILE + 4);  // t-pairs 2,3
                float4 ea = *(const float4*)(epA + d * K_TILE);   // k: 4kg..4kg+3
                float4 eb = *(const float4*)(epB + d * K_TILE);   // k: 64+4kg..+3
                unsigned long long e0 = dup2(ea.x), e1 = dup2(ea.y);
                unsigned long long e2 = dup2(ea.z), e3 = dup2(ea.w);
                unsigned long long e4 = dup2(eb.x), e5 = dup2(eb.y);
                unsigned long long e6 = dup2(eb.z), e7 = dup2(eb.w);
                FFMA2(acc[0][0], xa.x, e0); FFMA2(acc[1][0], xa.y, e0);
                FFMA2(acc[2][0], xb.x, e0); FFMA2(acc[3][0], xb.y, e0);
                FFMA2(acc[0][1], xa.x, e1); FFMA2(acc[1][1], xa.y, e1);
                FFMA2(acc[2][1], xb.x, e1); FFMA2(acc[3][1], xb.y, e1);
                FFMA2(acc[0][2], xa.x, e2); FFMA2(acc[1][2], xa.y, e2);
                FFMA2(acc[2][2], xb.x, e2); FFMA2(acc[3][2], xb.y, e2);
                FFMA2(acc[0][3], xa.x, e3); FFMA2(acc[1][3], xa.y, e3);
                FFMA2(acc[2][3], xb.x, e3); FFMA2(acc[3][3], xb.y, e3);
                FFMA2(acc[0][4], xa.x, e4); FFMA2(acc[1][4], xa.y, e4);
                FFMA2(acc[2][4], xb.x, e4); FFMA2(acc[3][4], xb.y, e4);
                FFMA2(acc[0][5], xa.x, e5); FFMA2(acc[1][5], xa.y, e5);
                FFMA2(acc[2][5], xb.x, e5); FFMA2(acc[3][5], xb.y, e5);
                FFMA2(acc[0][6], xa.x, e6); FFMA2(acc[1][6], xa.y, e6);
                FFMA2(acc[2][6], xb.x, e6); FFMA2(acc[3][6], xb.y, e6);
                FFMA2(acc[0][7], xa.x, e7); FFMA2(acc[1][7], xa.y, e7);
                FFMA2(acc[2][7], xb.x, e7); FFMA2(acc[3][7], xb.y, e7);
            }

            // distances exactly in reference form: fl(fl(X - 2s) + h); ascending-k, strict <
            #pragma unroll
            for (int tp = 0; tp < 4; tp++) {
                #pragma unroll
                for (int j = 0; j < 8; j++) {
                    int kk = (j < 4) ? (kg * 4 + j) : (64 + kg * 4 + (j - 4));
                    float h = sH[kk];
                    int kglob = kbase + kk;
                    float s_e = __uint_as_float((unsigned)(acc[tp][j]));
                    float s_o = __uint_as_float((unsigned)(acc[tp][j] >> 32));
                    float d_e = __fmaf_rn(-2.f, s_e, Xn[2 * tp]) + h;
                    float d_o = __fmaf_rn(-2.f, s_o, Xn[2 * tp + 1]) + h;
                    if (d_e < bestv[2 * tp])     { bestv[2 * tp] = d_e;     besti[2 * tp] = kglob; }
                    if (d_o < bestv[2 * tp + 1]) { bestv[2 * tp + 1] = d_o; besti[2 * tp + 1] = kglob; }
                }
            }
        }

        // ---- argmin reduction across kg threads (lowest index wins ties) ----
        #pragma unroll
        for (int i = 0; i < 8; i++) {
            sBV[(tg * 8 + i) * 16 + kg] = bestv[i];
            sBI[(tg * 8 + i) * 16 + kg] = besti[i];
        }
        __syncthreads();
        if (tid < T_TILE) {
            float bv = sBV[tid * 16]; int bi = sBI[tid * 16];
            #pragma unroll
            for (int j = 1; j < 16; j++) {
                float v = sBV[tid * 16 + j]; int ii = sBI[tid * 16 + j];
                if (v < bv || (v == bv && ii < bi)) { bv = v; bi = ii; }
            }
            sIdx[tid] = bi;
            atomicAdd(&g_cnt[phase][bi], 1);
        }
        __syncthreads();

        // ---- stage quant rows into smem (reuse sE), layout [d][t] like sX ----
        float* sQ = sE;
        for (int i = tid; i < T_TILE * 64; i += THREADS) {
            int t = i & 63, ds = i >> 6;
            float4 q = *(const float4*)&embp[(size_t)sIdx[t] * SUBD + ds * 4];
            sQ[(ds * 4 + 0) * T_TILE + t] = q.x;
            sQ[(ds * 4 + 1) * T_TILE + t] = q.y;
            sQ[(ds * 4 + 2) * T_TILE + t] = q.z;
            sQ[(ds * 4 + 3) * T_TILE + t] = q.w;
        }
        __syncthreads();

        // ---- write output (straight-through form x + (q - x)) + loss ----
        float* og = out + ((size_t)b * DD + phase * SUBD) * TT_SEQ + t0;
        for (int i = tid; i < SUBD * 16; i += THREADS) {
            int d = i >> 4, seg = i & 15;
            float4 q  = *(const float4*)&sQ[d * T_TILE + seg * 4];
            float4 xv = *(const float4*)&sX[d * T_TILE + seg * 4];
            float d0 = q.x - xv.x, d1 = q.y - xv.y, d2 = q.z - xv.z, d3 = q.w - xv.w;
            loss_acc += d0 * d0 + d1 * d1 + d2 * d2 + d3 * d3;
            float4 o;
            o.x = xv.x + d0; o.y = xv.y + d1; o.z = xv.z + d2; o.w = xv.w + d3;
            *(float4*)&og[(size_t)d * TT_SEQ + seg * 4] = o;
        }
        __syncthreads();   // before next phase reuses sX / sE
    }

    // ---- block loss reduction -> double atomic ----
    #pragma unroll
    for (int o = 16; o; o >>= 1) loss_acc += __shfl_down_sync(0xffffffffu, loss_acc, o);
    if ((tid & 31) == 0) warp_l[tid >> 5] = loss_acc;
    __syncthreads();
    if (tid == 0) {
        float s = 0.f;
        #pragma unroll
        for (int w = 0; w < 4; w++) s += warp_l[w];
        atomicAdd(&g_loss, (double)s);
    }
}

// ---------------------------------------------------------------- scalars

__global__ void finalize_k(float* __restrict__ out) {
    __shared__ double red0[8], red1[8];
    int tid = threadIdx.x;
    double s0 = 0.0, s1 = 0.0;
    for (int k = tid; k < KK; k += 256) {
        double p0 = (double)g_cnt[0][k] / (double)NROW;
        double p1 = (double)g_cnt[1][k] / (double)NROW;
        s0 += p0 * log(p0 + 1e-10);
        s1 += p1 * log(p1 + 1e-10);
    }
    #pragma unroll
    for (int o = 16; o; o >>= 1) {
        s0 += __shfl_down_sync(0xffffffffu, s0, o);
        s1 += __shfl_down_sync(0xffffffffu, s1, o);
    }
    if ((tid & 31) == 0) { red0[tid >> 5] = s0; red1[tid >> 5] = s1; }
    __syncthreads();
    if (tid == 0) {
        double e0 = 0.0, e1 = 0.0;
        #pragma unroll
        for (int w = 0; w < 8; w++) { e0 += red0[w]; e1 += red1[w]; }
        double perp = exp(-e0) + exp(-e1);
        double vq = 1.25 * g_loss / (double)NTOT;
        out[NTOT]     = (float)vq;
        out[NTOT + 1] = (float)perp;
    }
}

// ---------------------------------------------------------------- launch

extern "C" void kernel_launch(void* const* d_in, const int* in_sizes, int n_in,
                              void* d_out, int out_size) {
    const float* x  = (const float*)d_in[0];
    const float* e1 = (const float*)d_in[1];
    const float* e2 = (const float*)d_in[2];
    float* out = (float*)d_out;

    cudaFuncSetAttribute(vq_main, cudaFuncAttributeMaxDynamicSharedMemorySize, SMEM_BYTES);

    init_k<<<8, 256>>>();
    transpose_k<<<dim3(SUBD / 32, KK / 32, 2), dim3(32, 8)>>>(e1, e2);
    norm_k<<<256, 256>>>(e1, e2);
    vq_main<<<NBLOCKS, THREADS, SMEM_BYTES>>>(x, e1, e2, out);
    if (out_size >= NTOT + 2)
        finalize_k<<<1, 256>>>(out);
}

// round 5
// speedup vs baseline: 1.4103x; 1.1584x over previous
#include <cuda_runtime.h>
#include <math.h>

#define BB 16
#define TT_SEQ 4096
#define DD 512
#define SUBD 256
#define KK 1024
#define NROW (BB * TT_SEQ)          // 65536
#define NTOT (BB * DD * TT_SEQ)     // 33554432

#define T_TILE 64
#define K_TILE 128
#define THREADS 256
#define NBLOCKS ((NROW) / T_TILE)   // 1024

// dynamic smem layout (floats):
// sX: 256*64 | sE: 256*128 | sH: 128 | sXn: 64 | sBV: 1024 | sBI: 1024 | sIdx: 64 | sP: 256
#define SMEM_FLOATS (SUBD*T_TILE + SUBD*K_TILE + K_TILE + T_TILE + T_TILE*16 + T_TILE*16 + T_TILE + 4*T_TILE)
#define SMEM_BYTES (SMEM_FLOATS * 4)

__device__ float  g_eT[2][SUBD * KK];   // transposed codebooks: [d][k]
__device__ float  g_h[2][KK];           // ||e_k||^2
__device__ int    g_cnt[2][KK];
__device__ double g_loss;

// ---------------------------------------------------------------- helpers

__device__ __forceinline__ unsigned long long dup2(float v) {
    unsigned long long r;
    unsigned u = __float_as_uint(v);
    asm("mov.b64 %0, {%1, %1};" : "=l"(r) : "r"(u));
    return r;
}

#define FFMA2(acc, a, b) \
    asm("fma.rn.f32x2 %0, %1, %2, %0;" : "+l"(acc) : "l"(a), "l"(b))

// ---------------------------------------------------------------- init

__global__ void init_k() {
    int i = blockIdx.x * blockDim.x + threadIdx.x;
    if (i < 2 * KK) ((int*)g_cnt)[i] = 0;
    if (i == 0) g_loss = 0.0;
}

// ---------------------------------------------------------------- transpose emb -> g_eT [d][k]

__global__ void transpose_k(const float* __restrict__ e1, const float* __restrict__ e2) {
    __shared__ float tile[32][33];
    int c = blockIdx.z;
    const float* src = c ? e2 : e1;
    int row0 = blockIdx.y * 32;   // k
    int col0 = blockIdx.x * 32;   // d
    int tx = threadIdx.x, ty = threadIdx.y;    // 32 x 8
    #pragma unroll
    for (int j = 0; j < 32; j += 8)
        tile[ty + j][tx] = src[(size_t)(row0 + ty + j) * SUBD + col0 + tx];
    __syncthreads();
    #pragma unroll
    for (int j = 0; j < 32; j += 8)
        g_eT[c][(size_t)(col0 + ty + j) * KK + row0 + tx] = tile[tx][ty + j];
}

// ---------------------------------------------------------------- codeword norms

__global__ void norm_k(const float* __restrict__ e1, const float* __restrict__ e2) {
    int warp = threadIdx.x >> 5, lane = threadIdx.x & 31;
    int c = blockIdx.x >> 7;
    int row = ((blockIdx.x & 127) << 3) + warp;
    const float* src = c ? e2 : e1;
    const float4* r = (const float4*)(src + (size_t)row * SUBD);
    float4 a = r[lane], b = r[lane + 32];
    float s = a.x*a.x + a.y*a.y + a.z*a.z + a.w*a.w
            + b.x*b.x + b.y*b.y + b.z*b.z + b.w*b.w;
    #pragma unroll
    for (int o = 16; o; o >>= 1) s += __shfl_down_sync(0xffffffffu, s, o);
    if (lane == 0) g_h[c][row] = s;
}

// ---------------------------------------------------------------- main VQ kernel
// 256 threads (8 warps -> 2 per SMSP): tg = tid>>4 (16 groups of 4 t),
// kg = tid&15 owns k in {4kg..4kg+3} u {64+4kg..64+4kg+3} (contiguous 16B
// float4 LDS -> conflict-free). Accumulators pack K-PAIRS per f32x2 (the
// float4 e-load IS two packed pairs -> zero e-dups; 4 x-dups per d).
// Micro-tile 4t x 8k = 16 FFMA2/d/thread; 23 instr per 16 FFMA2.

__global__ void __launch_bounds__(THREADS, 1) vq_main(
    const float* __restrict__ x, const float* __restrict__ emb1,
    const float* __restrict__ emb2, float* __restrict__ out)
{
    extern __shared__ float sm[];
    float* sX   = sm;                           // [256][64]  x tile, d-major, t contiguous
    float* sE   = sX + SUBD * T_TILE;           // [256][128] codebook tile, d-major, k contiguous
    float* sH   = sE + SUBD * K_TILE;           // [128]
    float* sXn  = sH + K_TILE;                  // [64] row norms
    float* sBV  = sXn + T_TILE;                 // [64][16]
    int*   sBI  = (int*)(sBV + T_TILE * 16);    // [64][16]
    int*   sIdx = sBI + T_TILE * 16;            // [64]
    float* sP   = (float*)(sIdx + T_TILE);      // [4][64] partial norms
    __shared__ float warp_l[8];

    int tid = threadIdx.x;
    int tg = tid >> 4;        // 0..15 -> t group (4 t's)
    int kg = tid & 15;        // 0..15 -> k group (8 k's, split 4+4)
    int blk = blockIdx.x;
    int b = blk >> 6;
    int t0 = (blk & 63) * T_TILE;

    float loss_acc = 0.f;

    for (int phase = 0; phase < 2; ++phase) {
        const float* xg   = x + ((size_t)b * DD + phase * SUBD) * TT_SEQ + t0;
        const float* eT   = g_eT[phase];
        const float* hh   = g_h[phase];
        const float* embp = phase ? emb2 : emb1;

        // ---- load x tile (coalesced, conflict-free) ----
        for (int i = tid; i < SUBD * 16; i += THREADS) {
            int d = i >> 4, seg = i & 15;
            *(float4*)&sX[d * T_TILE + seg * 4] =
                *(const float4*)&xg[(size_t)d * TT_SEQ + seg * 4];
        }
        __syncthreads();

        // ---- row norms X[t]: EXACT same 4x64-chunk grouping as passing versions ----
        {
            int t = tid & 63, c = tid >> 6;
            float s = 0.f;
            #pragma unroll 8
            for (int d = c * 64; d < c * 64 + 64; ++d) {
                float v = sX[d * T_TILE + t];
                s = fmaf(v, v, s);
            }
            sP[c * T_TILE + t] = s;
        }
        __syncthreads();
        if (tid < T_TILE)
            sXn[tid] = ((sP[tid] + sP[T_TILE + tid]) + sP[2 * T_TILE + tid]) + sP[3 * T_TILE + tid];
        __syncthreads();

        float Xn[4];
        #pragma unroll
        for (int i = 0; i < 4; i++) Xn[i] = sXn[tg * 4 + i];

        float bestv[4]; int besti[4];
        #pragma unroll
        for (int i = 0; i < 4; i++) { bestv[i] = 3.4e38f; besti[i] = 0; }

        // ---- K tiles ----
        for (int kt = 0; kt < KK / K_TILE; ++kt) {
            int kbase = kt * K_TILE;
            __syncthreads();   // previous tile fully consumed
            for (int i = tid; i < SUBD * 32; i += THREADS) {
                int d = i >> 5, c = i & 31;
                *(float4*)&sE[d * K_TILE + c * 4] =
                    *(const float4*)&eT[(size_t)d * KK + kbase + c * 4];
            }
            if (tid < K_TILE) sH[tid] = hh[kbase + tid];
            __syncthreads();

            // acc[i][j]: i = t slot (t = tg*4+i), j = k-pair slot
            // j=0: k 4kg+{0,1}  j=1: k 4kg+{2,3}  j=2: 64+4kg+{0,1}  j=3: 64+4kg+{2,3}
            unsigned long long acc[4][4];
            #pragma unroll
            for (int i = 0; i < 4; i++)
                #pragma unroll
                for (int j = 0; j < 4; j++) acc[i][j] = 0ULL;

            const float* xp  = &sX[tg * 4];
            const float* epA = &sE[kg * 4];
            const float* epB = &sE[64 + kg * 4];
            #pragma unroll 4
            for (int d = 0; d < SUBD; ++d) {
                float4 xf = *(const float4*)(xp + d * T_TILE);              // 4 t's
                ulonglong2 eA = *(const ulonglong2*)(epA + d * K_TILE);     // k-pairs 0,1
                ulonglong2 eB = *(const ulonglong2*)(epB + d * K_TILE);     // k-pairs 2,3
                unsigned long long x0 = dup2(xf.x), x1 = dup2(xf.y);
                unsigned long long x2 = dup2(xf.z), x3 = dup2(xf.w);
                FFMA2(acc[0][0], x0, eA.x); FFMA2(acc[0][1], x0, eA.y);
                FFMA2(acc[0][2], x0, eB.x); FFMA2(acc[0][3], x0, eB.y);
                FFMA2(acc[1][0], x1, eA.x); FFMA2(acc[1][1], x1, eA.y);
                FFMA2(acc[1][2], x1, eB.x); FFMA2(acc[1][3], x1, eB.y);
                FFMA2(acc[2][0], x2, eA.x); FFMA2(acc[2][1], x2, eA.y);
                FFMA2(acc[2][2], x2, eB.x); FFMA2(acc[2][3], x2, eB.y);
                FFMA2(acc[3][0], x3, eA.x); FFMA2(acc[3][1], x3, eA.y);
                FFMA2(acc[3][2], x3, eB.x); FFMA2(acc[3][3], x3, eB.y);
            }

            // distances exactly in reference form: fl(fl(X - 2s) + h); ascending-k, strict <
            #pragma unroll
            for (int i = 0; i < 4; i++) {
                #pragma unroll
                for (int j = 0; j < 4; j++) {
                    int kk = (j < 2) ? (kg * 4 + j * 2) : (64 + kg * 4 + (j - 2) * 2);
                    float h0 = sH[kk], h1 = sH[kk + 1];
                    int kglob = kbase + kk;
                    float s0 = __uint_as_float((unsigned)(acc[i][j]));
                    float s1 = __uint_as_float((unsigned)(acc[i][j] >> 32));
                    float d0 = __fmaf_rn(-2.f, s0, Xn[i]) + h0;
                    float d1 = __fmaf_rn(-2.f, s1, Xn[i]) + h1;
                    if (d0 < bestv[i]) { bestv[i] = d0; besti[i] = kglob; }
                    if (d1 < bestv[i]) { bestv[i] = d1; besti[i] = kglob + 1; }
                }
            }
        }

        // ---- argmin reduction across kg threads (lowest index wins ties) ----
        #pragma unroll
        for (int i = 0; i < 4; i++) {
            sBV[(tg * 4 + i) * 16 + kg] = bestv[i];
            sBI[(tg * 4 + i) * 16 + kg] = besti[i];
        }
        __syncthreads();
        if (tid < T_TILE) {
            float bv = sBV[tid * 16]; int bi = sBI[tid * 16];
            #pragma unroll
            for (int j = 1; j < 16; j++) {
                float v = sBV[tid * 16 + j]; int ii = sBI[tid * 16 + j];
                if (v < bv || (v == bv && ii < bi)) { bv = v; bi = ii; }
            }
            sIdx[tid] = bi;
            atomicAdd(&g_cnt[phase][bi], 1);
        }
        __syncthreads();

        // ---- stage quant rows into smem (reuse sE), layout [d][t] like sX ----
        float* sQ = sE;
        for (int i = tid; i < T_TILE * 64; i += THREADS) {
            int t = i & 63, ds = i >> 6;
            float4 q = *(const float4*)&embp[(size_t)sIdx[t] * SUBD + ds * 4];
            sQ[(ds * 4 + 0) * T_TILE + t] = q.x;
            sQ[(ds * 4 + 1) * T_TILE + t] = q.y;
            sQ[(ds * 4 + 2) * T_TILE + t] = q.z;
            sQ[(ds * 4 + 3) * T_TILE + t] = q.w;
        }
        __syncthreads();

        // ---- write output (straight-through form x + (q - x)) + loss ----
        float* og = out + ((size_t)b * DD + phase * SUBD) * TT_SEQ + t0;
        for (int i = tid; i < SUBD * 16; i += THREADS) {
            int d = i >> 4, seg = i & 15;
            float4 q  = *(const float4*)&sQ[d * T_TILE + seg * 4];
            float4 xv = *(const float4*)&sX[d * T_TILE + seg * 4];
            float d0 = q.x - xv.x, d1 = q.y - xv.y, d2 = q.z - xv.z, d3 = q.w - xv.w;
            loss_acc += d0 * d0 + d1 * d1 + d2 * d2 + d3 * d3;
            float4 o;
            o.x = xv.x + d0; o.y = xv.y + d1; o.z = xv.z + d2; o.w = xv.w + d3;
            *(float4*)&og[(size_t)d * TT_SEQ + seg * 4] = o;
        }
        __syncthreads();   // before next phase reuses sX / sE
    }

    // ---- block loss reduction -> double atomic ----
    #pragma unroll
    for (int o = 16; o; o >>= 1) loss_acc += __shfl_down_sync(0xffffffffu, loss_acc, o);
    if ((tid & 31) == 0) warp_l[tid >> 5] = loss_acc;
    __syncthreads();
    if (tid == 0) {
        float s = 0.f;
        #pragma unroll
        for (int w = 0; w < 8; w++) s += warp_l[w];
        atomicAdd(&g_loss, (double)s);
    }
}

// ---------------------------------------------------------------- scalars

__global__ void finalize_k(float* __restrict__ out) {
    __shared__ double red0[8], red1[8];
    int tid = threadIdx.x;
    double s0 = 0.0, s1 = 0.0;
    for (int k = tid; k < KK; k += 256) {
        double p0 = (double)g_cnt[0][k] / (double)NROW;
        double p1 = (double)g_cnt[1][k] / (double)NROW;
        s0 += p0 * log(p0 + 1e-10);
        s1 += p1 * log(p1 + 1e-10);
    }
    #pragma unroll
    for (int o = 16; o; o >>= 1) {
        s0 += __shfl_down_sync(0xffffffffu, s0, o);
        s1 += __shfl_down_sync(0xffffffffu, s1, o);
    }
    if ((tid & 31) == 0) { red0[tid >> 5] = s0; red1[tid >> 5] = s1; }
    __syncthreads();
    if (tid == 0) {
        double e0 = 0.0, e1 = 0.0;
        #pragma unroll
        for (int w = 0; w < 8; w++) { e0 += red0[w]; e1 += red1[w]; }
        double perp = exp(-e0) + exp(-e1);
        double vq = 1.25 * g_loss / (double)NTOT;
        out[NTOT]     = (float)vq;
        out[NTOT + 1] = (float)perp;
    }
}

// ---------------------------------------------------------------- launch

extern "C" void kernel_launch(void* const* d_in, const int* in_sizes, int n_in,
                              void* d_out, int out_size) {
    const float* x  = (const float*)d_in[0];
    const float* e1 = (const float*)d_in[1];
    const float* e2 = (const float*)d_in[2];
    float* out = (float*)d_out;

    cudaFuncSetAttribute(vq_main, cudaFuncAttributeMaxDynamicSharedMemorySize, SMEM_BYTES);

    init_k<<<8, 256>>>();
    transpose_k<<<dim3(SUBD / 32, KK / 32, 2), dim3(32, 8)>>>(e1, e2);
    norm_k<<<256, 256>>>(e1, e2);
    vq_main<<<NBLOCKS, THREADS, SMEM_BYTES>>>(x, e1, e2, out);
    if (out_size >= NTOT + 2)
        finalize_k<<<1, 256>>>(out);
}

// round 6
// speedup vs baseline: 1.4599x; 1.0352x over previous
#include <cuda_runtime.h>
#include <math.h>

#define BB 16
#define TT_SEQ 4096
#define DD 512
#define SUBD 256
#define KK 1024
#define NROW (BB * TT_SEQ)          // 65536
#define NTOT (BB * DD * TT_SEQ)     // 33554432

#define T_TILE 64
#define K_TILE 128
#define THREADS 256
#define NBLOCKS ((NROW) / T_TILE)   // 1024

// dynamic smem layout (floats):
// sX: 256*64 | sE: 256*128 | sH: 128 | sXn: 64 | sBV: 1024 | sBI: 1024 | sIdx: 64 | sP: 256
#define SMEM_FLOATS (SUBD*T_TILE + SUBD*K_TILE + K_TILE + T_TILE + T_TILE*16 + T_TILE*16 + T_TILE + 4*T_TILE)
#define SMEM_BYTES (SMEM_FLOATS * 4)

__device__ float  g_eT[2][SUBD * KK];   // transposed codebooks: [d][k]
__device__ float  g_h[2][KK];           // ||e_k||^2
__device__ int    g_cnt[2][KK];
__device__ double g_loss;

// ---------------------------------------------------------------- helpers

__device__ __forceinline__ unsigned long long dup2(float v) {
    unsigned long long r;
    unsigned u = __float_as_uint(v);
    asm("mov.b64 %0, {%1, %1};" : "=l"(r) : "r"(u));
    return r;
}

#define FFMA2(acc, a, b) \
    asm("fma.rn.f32x2 %0, %1, %2, %0;" : "+l"(acc) : "l"(a), "l"(b))

// ---------------------------------------------------------------- init

__global__ void init_k() {
    int i = blockIdx.x * blockDim.x + threadIdx.x;
    if (i < 2 * KK) ((int*)g_cnt)[i] = 0;
    if (i == 0) g_loss = 0.0;
}

// ---------------------------------------------------------------- transpose emb -> g_eT [d][k]

__global__ void transpose_k(const float* __restrict__ e1, const float* __restrict__ e2) {
    __shared__ float tile[32][33];
    int c = blockIdx.z;
    const float* src = c ? e2 : e1;
    int row0 = blockIdx.y * 32;   // k
    int col0 = blockIdx.x * 32;   // d
    int tx = threadIdx.x, ty = threadIdx.y;    // 32 x 8
    #pragma unroll
    for (int j = 0; j < 32; j += 8)
        tile[ty + j][tx] = src[(size_t)(row0 + ty + j) * SUBD + col0 + tx];
    __syncthreads();
    #pragma unroll
    for (int j = 0; j < 32; j += 8)
        g_eT[c][(size_t)(col0 + ty + j) * KK + row0 + tx] = tile[tx][ty + j];
}

// ---------------------------------------------------------------- codeword norms

__global__ void norm_k(const float* __restrict__ e1, const float* __restrict__ e2) {
    int warp = threadIdx.x >> 5, lane = threadIdx.x & 31;
    int c = blockIdx.x >> 7;
    int row = ((blockIdx.x & 127) << 3) + warp;
    const float* src = c ? e2 : e1;
    const float4* r = (const float4*)(src + (size_t)row * SUBD);
    float4 a = r[lane], b = r[lane + 32];
    float s = a.x*a.x + a.y*a.y + a.z*a.z + a.w*a.w
            + b.x*b.x + b.y*b.y + b.z*b.z + b.w*b.w;
    #pragma unroll
    for (int o = 16; o; o >>= 1) s += __shfl_down_sync(0xffffffffu, s, o);
    if (lane == 0) g_h[c][row] = s;
}

// ---------------------------------------------------------------- main VQ kernel
// 256 threads (8 warps -> 2 per SMSP). tg = tid>>4 (16 groups of 4 t),
// kg = tid&15 owns k in {4kg..4kg+3} u {64+4kg..64+4kg+3}.
// k-pair packed accumulators (float4 e-load = 2 f32x2 operands, zero e-dups).
// Software-pipelined d-loop: prefetch d+1 while computing d (covers LDS lat).

__global__ void __launch_bounds__(THREADS, 1) vq_main(
    const float* __restrict__ x, const float* __restrict__ emb1,
    const float* __restrict__ emb2, float* __restrict__ out)
{
    extern __shared__ float sm[];
    float* sX   = sm;                           // [256][64]  x tile, d-major, t contiguous
    float* sE   = sX + SUBD * T_TILE;           // [256][128] codebook tile, d-major, k contiguous
    float* sH   = sE + SUBD * K_TILE;           // [128]
    float* sXn  = sH + K_TILE;                  // [64] row norms
    float* sBV  = sXn + T_TILE;                 // [64][16]
    int*   sBI  = (int*)(sBV + T_TILE * 16);    // [64][16]
    int*   sIdx = sBI + T_TILE * 16;            // [64]
    float* sP   = (float*)(sIdx + T_TILE);      // [4][64] partial norms
    __shared__ float warp_l[8];

    int tid = threadIdx.x;
    int tg = tid >> 4;        // 0..15 -> t group (4 t's)
    int kg = tid & 15;        // 0..15 -> k group (8 k's, split 4+4)
    int blk = blockIdx.x;
    int b = blk >> 6;
    int t0 = (blk & 63) * T_TILE;

    float loss_acc = 0.f;

    for (int phase = 0; phase < 2; ++phase) {
        const float* xg   = x + ((size_t)b * DD + phase * SUBD) * TT_SEQ + t0;
        const float* eT   = g_eT[phase];
        const float* hh   = g_h[phase];
        const float* embp = phase ? emb2 : emb1;

        // ---- load x tile (coalesced, conflict-free) ----
        for (int i = tid; i < SUBD * 16; i += THREADS) {
            int d = i >> 4, seg = i & 15;
            *(float4*)&sX[d * T_TILE + seg * 4] =
                *(const float4*)&xg[(size_t)d * TT_SEQ + seg * 4];
        }
        __syncthreads();

        // ---- row norms X[t]: EXACT same 4x64-chunk grouping as passing versions ----
        {
            int t = tid & 63, c = tid >> 6;
            float s = 0.f;
            #pragma unroll 8
            for (int d = c * 64; d < c * 64 + 64; ++d) {
                float v = sX[d * T_TILE + t];
                s = fmaf(v, v, s);
            }
            sP[c * T_TILE + t] = s;
        }
        __syncthreads();
        if (tid < T_TILE)
            sXn[tid] = ((sP[tid] + sP[T_TILE + tid]) + sP[2 * T_TILE + tid]) + sP[3 * T_TILE + tid];
        __syncthreads();

        float Xn[4];
        #pragma unroll
        for (int i = 0; i < 4; i++) Xn[i] = sXn[tg * 4 + i];

        float bestv[4]; int besti[4];
        #pragma unroll
        for (int i = 0; i < 4; i++) { bestv[i] = 3.4e38f; besti[i] = 0; }

        // ---- K tiles ----
        for (int kt = 0; kt < KK / K_TILE; ++kt) {
            int kbase = kt * K_TILE;
            __syncthreads();   // previous tile fully consumed
            for (int i = tid; i < SUBD * 32; i += THREADS) {
                int d = i >> 5, c = i & 31;
                *(float4*)&sE[d * K_TILE + c * 4] =
                    *(const float4*)&eT[(size_t)d * KK + kbase + c * 4];
            }
            if (tid < K_TILE) sH[tid] = hh[kbase + tid];
            __syncthreads();

            // acc[i][j]: i = t slot (t = tg*4+i), j = k-pair slot
            // j=0: k 4kg+{0,1}  j=1: k 4kg+{2,3}  j=2: 64+4kg+{0,1}  j=3: 64+4kg+{2,3}
            unsigned long long acc[4][4];
            #pragma unroll
            for (int i = 0; i < 4; i++)
                #pragma unroll
                for (int j = 0; j < 4; j++) acc[i][j] = 0ULL;

            const float* xp  = &sX[tg * 4];
            const float* epA = &sE[kg * 4];
            const float* epB = &sE[64 + kg * 4];

            // software pipeline: cur = d, prefetch d+1 before computing.
            // d=255 prefetch reads one row past sX/sE -> lands inside the
            // allocated smem (sE / sH regions), value never consumed.
            float4 xf = *(const float4*)(xp);
            ulonglong2 eA = *(const ulonglong2*)(epA);
            ulonglong2 eB = *(const ulonglong2*)(epB);
            #pragma unroll 4
            for (int d = 0; d < SUBD; ++d) {
                float4 xf_n = *(const float4*)(xp + (d + 1) * T_TILE);
                ulonglong2 eA_n = *(const ulonglong2*)(epA + (d + 1) * K_TILE);
                ulonglong2 eB_n = *(const ulonglong2*)(epB + (d + 1) * K_TILE);
                unsigned long long x0 = dup2(xf.x), x1 = dup2(xf.y);
                unsigned long long x2 = dup2(xf.z), x3 = dup2(xf.w);
                FFMA2(acc[0][0], x0, eA.x); FFMA2(acc[0][1], x0, eA.y);
                FFMA2(acc[0][2], x0, eB.x); FFMA2(acc[0][3], x0, eB.y);
                FFMA2(acc[1][0], x1, eA.x); FFMA2(acc[1][1], x1, eA.y);
                FFMA2(acc[1][2], x1, eB.x); FFMA2(acc[1][3], x1, eB.y);
                FFMA2(acc[2][0], x2, eA.x); FFMA2(acc[2][1], x2, eA.y);
                FFMA2(acc[2][2], x2, eB.x); FFMA2(acc[2][3], x2, eB.y);
                FFMA2(acc[3][0], x3, eA.x); FFMA2(acc[3][1], x3, eA.y);
                FFMA2(acc[3][2], x3, eB.x); FFMA2(acc[3][3], x3, eB.y);
                xf = xf_n; eA = eA_n; eB = eB_n;
            }

            // distances exactly in reference form: fl(fl(X - 2s) + h); ascending-k, strict <
            #pragma unroll
            for (int i = 0; i < 4; i++) {
                #pragma unroll
                for (int j = 0; j < 4; j++) {
                    int kk = (j < 2) ? (kg * 4 + j * 2) : (64 + kg * 4 + (j - 2) * 2);
                    float h0 = sH[kk], h1 = sH[kk + 1];
                    int kglob = kbase + kk;
                    float s0 = __uint_as_float((unsigned)(acc[i][j]));
                    float s1 = __uint_as_float((unsigned)(acc[i][j] >> 32));
                    float d0 = __fmaf_rn(-2.f, s0, Xn[i]) + h0;
                    float d1 = __fmaf_rn(-2.f, s1, Xn[i]) + h1;
                    if (d0 < bestv[i]) { bestv[i] = d0; besti[i] = kglob; }
                    if (d1 < bestv[i]) { bestv[i] = d1; besti[i] = kglob + 1; }
                }
            }
        }

        // ---- argmin reduction across kg threads (lowest index wins ties) ----
        #pragma unroll
        for (int i = 0; i < 4; i++) {
            sBV[(tg * 4 + i) * 16 + kg] = bestv[i];
            sBI[(tg * 4 + i) * 16 + kg] = besti[i];
        }
        __syncthreads();
        if (tid < T_TILE) {
            float bv = sBV[tid * 16]; int bi = sBI[tid * 16];
            #pragma unroll
            for (int j = 1; j < 16; j++) {
                float v = sBV[tid * 16 + j]; int ii = sBI[tid * 16 + j];
                if (v < bv || (v == bv && ii < bi)) { bv = v; bi = ii; }
            }
            sIdx[tid] = bi;
            atomicAdd(&g_cnt[phase][bi], 1);
        }
        __syncthreads();

        // ---- stage quant rows into smem (reuse sE), layout [d][t] like sX ----
        float* sQ = sE;
        for (int i = tid; i < T_TILE * 64; i += THREADS) {
            int t = i & 63, ds = i >> 6;
            float4 q = *(const float4*)&embp[(size_t)sIdx[t] * SUBD + ds * 4];
            sQ[(ds * 4 + 0) * T_TILE + t] = q.x;
            sQ[(ds * 4 + 1) * T_TILE + t] = q.y;
            sQ[(ds * 4 + 2) * T_TILE + t] = q.z;
            sQ[(ds * 4 + 3) * T_TILE + t] = q.w;
        }
        __syncthreads();

        // ---- write output (straight-through form x + (q - x)) + loss ----
        float* og = out + ((size_t)b * DD + phase * SUBD) * TT_SEQ + t0;
        for (int i = tid; i < SUBD * 16; i += THREADS) {
            int d = i >> 4, seg = i & 15;
            float4 q  = *(const float4*)&sQ[d * T_TILE + seg * 4];
            float4 xv = *(const float4*)&sX[d * T_TILE + seg * 4];
            float d0 = q.x - xv.x, d1 = q.y - xv.y, d2 = q.z - xv.z, d3 = q.w - xv.w;
            loss_acc += d0 * d0 + d1 * d1 + d2 * d2 + d3 * d3;
            float4 o;
            o.x = xv.x + d0; o.y = xv.y + d1; o.z = xv.z + d2; o.w = xv.w + d3;
            *(float4*)&og[(size_t)d * TT_SEQ + seg * 4] = o;
        }
        __syncthreads();   // before next phase reuses sX / sE
    }

    // ---- block loss reduction -> double atomic ----
    #pragma unroll
    for (int o = 16; o; o >>= 1) loss_acc += __shfl_down_sync(0xffffffffu, loss_acc, o);
    if ((tid & 31) == 0) warp_l[tid >> 5] = loss_acc;
    __syncthreads();
    if (tid == 0) {
        float s = 0.f;
        #pragma unroll
        for (int w = 0; w < 8; w++) s += warp_l[w];
        atomicAdd(&g_loss, (double)s);
    }
}

// ---------------------------------------------------------------- scalars

__global__ void finalize_k(float* __restrict__ out) {
    __shared__ double red0[8], red1[8];
    int tid = threadIdx.x;
    double s0 = 0.0, s1 = 0.0;
    for (int k = tid; k < KK; k += 256) {
        double p0 = (double)g_cnt[0][k] / (double)NROW;
        double p1 = (double)g_cnt[1][k] / (double)NROW;
        s0 += p0 * log(p0 + 1e-10);
        s1 += p1 * log(p1 + 1e-10);
    }
    #pragma unroll
    for (int o = 16; o; o >>= 1) {
        s0 += __shfl_down_sync(0xffffffffu, s0, o);
        s1 += __shfl_down_sync(0xffffffffu, s1, o);
    }
    if ((tid & 31) == 0) { red0[tid >> 5] = s0; red1[tid >> 5] = s1; }
    __syncthreads();
    if (tid == 0) {
        double e0 = 0.0, e1 = 0.0;
        #pragma unroll
        for (int w = 0; w < 8; w++) { e0 += red0[w]; e1 += red1[w]; }
        double perp = exp(-e0) + exp(-e1);
        double vq = 1.25 * g_loss / (double)NTOT;
        out[NTOT]     = (float)vq;
        out[NTOT + 1] = (float)perp;
    }
}

// ---------------------------------------------------------------- launch

extern "C" void kernel_launch(void* const* d_in, const int* in_sizes, int n_in,
                              void* d_out, int out_size) {
    const float* x  = (const float*)d_in[0];
    const float* e1 = (const float*)d_in[1];
    const float* e2 = (const float*)d_in[2];
    float* out = (float*)d_out;

    cudaFuncSetAttribute(vq_main, cudaFuncAttributeMaxDynamicSharedMemorySize, SMEM_BYTES);

    init_k<<<8, 256>>>();
    transpose_k<<<dim3(SUBD / 32, KK / 32, 2), dim3(32, 8)>>>(e1, e2);
    norm_k<<<256, 256>>>(e1, e2);
    vq_main<<<NBLOCKS, THREADS, SMEM_BYTES>>>(x, e1, e2, out);
    if (out_size >= NTOT + 2)
        finalize_k<<<1, 256>>>(out);
}